// round 16
// baseline (speedup 1.0000x reference)
#include <cuda_runtime.h>
#include <mma.h>
#include <math.h>
#include <cstdint>

#define DIM    2048
#define SEQ    2048
#define BATCH  2
#define HEADS  16
#define HDIM   128
#define MROWS  (BATCH*SEQ)   /* 4096 */
#define NM16   (MROWS/16)    /* 256 m16 blocks  */
#define NN8    (DIM/8)       /* 256 n8 blocks   */

// ---------------- scratch (device globals; no allocations) ----------------
__device__ float g_q[(size_t)MROWS * DIM];       // Q proj, row-major (pre-rmsnorm)
__device__ float g_k[(size_t)MROWS * DIM];       // K proj, row-major (pre-rmsnorm)
__device__ float g_v[(size_t)MROWS * DIM];       // V packed B-frag per (b,h)
__device__ float g_attn[(size_t)MROWS * DIM];    // attention out, row-major
__device__ float g_xr[(size_t)MROWS * DIM];      // packed x / packed K / packed attn
__device__ float g_qp[(size_t)MROWS * DIM];      // packed Q (A-frag per b,h)
__device__ float g_wr4[(size_t)4 * DIM * DIM];   // packed Wq|Wk|Wv|Wo

// ---------------- cp.async helpers ----------------
__device__ __forceinline__ void cp_async16(void* dst, const void* src) {
    unsigned d = (unsigned)__cvta_generic_to_shared(dst);
    asm volatile("cp.async.cg.shared.global [%0], [%1], 16;\n" :: "r"(d), "l"(src));
}
#define CP_COMMIT() asm volatile("cp.async.commit_group;\n" ::: "memory")
#define CP_WAIT(n)  asm volatile("cp.async.wait_group %0;\n" :: "n"(n) : "memory")

// ---------------- raw tf32 mma (m16n8k8, row.col, fp32 accum) ----------------
__device__ __forceinline__ void mma_tf32(float d[4], const uint32_t a[4],
                                         const uint32_t b[2]) {
    asm volatile(
        "mma.sync.aligned.m16n8k8.row.col.f32.tf32.tf32.f32 "
        "{%0,%1,%2,%3}, {%4,%5,%6,%7}, {%8,%9}, {%0,%1,%2,%3};\n"
        : "+f"(d[0]), "+f"(d[1]), "+f"(d[2]), "+f"(d[3])
        : "r"(a[0]), "r"(a[1]), "r"(a[2]), "r"(a[3]), "r"(b[0]), "r"(b[1]));
}
__device__ __forceinline__ uint32_t f2u(float f) { return __float_as_uint(f); }
__device__ __forceinline__ float rtf32(float f) { return nvcuda::wmma::__float_to_tf32(f); }

// ============================================================================
// Repack A (row-major [M][2048]) -> PA[k8][m16][128] + rtf32.
// ============================================================================
__global__ __launch_bounds__(256) void repack_a_kernel(
    const float* __restrict__ src, float* __restrict__ dst)
{
    __shared__ float ts[64][33];
    const int bx = blockIdx.x;
    const int by = blockIdx.y;
    const int tid = threadIdx.x;

#pragma unroll
    for (int i = 0; i < 2; i++) {
        int idx = tid + i * 256;
        int row = idx >> 3, c4 = (idx & 7) << 2;
        float4 v = *(const float4*)&src[(size_t)(by * 64 + row) * DIM + bx * 32 + c4];
        ts[row][c4 + 0] = rtf32(v.x); ts[row][c4 + 1] = rtf32(v.y);
        ts[row][c4 + 2] = rtf32(v.z); ts[row][c4 + 3] = rtf32(v.w);
    }
    __syncthreads();

#pragma unroll
    for (int i = 0; i < 8; i++) {
        int o = tid + i * 256;
        int b = o >> 7, f = o & 127;
        int k8rel = b >> 2, m16rel = b & 3;
        int lane = f >> 2, r = f & 3;
        int row = m16rel * 16 + (lane >> 2) + ((r & 1) << 3);
        int col = k8rel * 8 + (lane & 3) + ((r >> 1) << 2);
        dst[((size_t)(bx * 4 + k8rel) * NM16 + by * 4 + m16rel) * 128 + f] = ts[row][col];
    }
}

// ============================================================================
// Repack B (weights [N][2048]) -> PB[k16][n8][128] + rtf32.
// ============================================================================
__global__ __launch_bounds__(256) void repack_b4_kernel(
    const float* __restrict__ w0, const float* __restrict__ w1,
    const float* __restrict__ w2, const float* __restrict__ w3,
    float* __restrict__ dst)
{
    __shared__ float ts[64][33];
    const int bx = blockIdx.x;
    const int by = blockIdx.y;
    const int w  = blockIdx.z;
    const int tid = threadIdx.x;
    const float* src = (w == 0) ? w0 : (w == 1) ? w1 : (w == 2) ? w2 : w3;
    float* d = dst + (size_t)w * DIM * DIM;

#pragma unroll
    for (int i = 0; i < 2; i++) {
        int idx = tid + i * 256;
        int row = idx >> 3, c4 = (idx & 7) << 2;
        float4 v = *(const float4*)&src[(size_t)(by * 64 + row) * DIM + bx * 32 + c4];
        ts[row][c4 + 0] = rtf32(v.x); ts[row][c4 + 1] = rtf32(v.y);
        ts[row][c4 + 2] = rtf32(v.z); ts[row][c4 + 3] = rtf32(v.w);
    }
    __syncthreads();

#pragma unroll
    for (int i = 0; i < 8; i++) {
        int o = tid + i * 256;
        int b = o >> 7, f = o & 127;
        int k16rel = b >> 3, n8rel = b & 7;
        int lane = f >> 2, r = f & 3;
        int row = n8rel * 8 + (lane >> 2);
        int col = k16rel * 16 + (lane & 3) + (r << 2);
        d[((size_t)(bx * 2 + k16rel) * NN8 + by * 8 + n8rel) * 128 + f] = ts[row][col];
    }
}

// ============================================================================
// NT GEMM on fragment-packed operands. CTA 128x128, 4 warps 64x64, K-tile 32,
// 3-stage cp.async. PACK_V: epilogue writes V in packed B-frag layout per (b,h).
// ============================================================================
#define GSTG 3
#define GSTAGE_F 4096
#define GEMM_SMEM_BYTES (2 * GSTG * GSTAGE_F * 4)   /* 98304 */

template <bool ADD_BIAS, bool PACK_V>
__global__ __launch_bounds__(128, 2) void gemm_mma_tf32(
    const float* __restrict__ A, const float* __restrict__ B,
    float* __restrict__ C, const float* __restrict__ bias)
{
    extern __shared__ float smg[];
    float* sA = smg;
    float* sB = smg + GSTG * GSTAGE_F;

    const int bm   = blockIdx.y * 128;
    const int bn   = blockIdx.x * 128;
    const int bm16 = blockIdx.y * 8;
    const int bn8  = blockIdx.x * 16;
    const int tid  = threadIdx.x;
    const int warp = tid >> 5;
    const int lane = tid & 31;
    const int g    = lane >> 2;
    const int tig  = lane & 3;
    const int wm = warp >> 1;
    const int wn = warp & 1;

    const int ntiles = DIM / 32;

    float acc[4][8][4];
#pragma unroll
    for (int i = 0; i < 4; i++)
#pragma unroll
        for (int j = 0; j < 8; j++)
#pragma unroll
            for (int t = 0; t < 4; t++) acc[i][j][t] = 0.f;

    auto issue_tile = [&](int t) {
        int s = t % GSTG;
        float* as = sA + s * GSTAGE_F;
        float* bs = sB + s * GSTAGE_F;
#pragma unroll
        for (int i = 0; i < 8; i++) {
            int c = tid + i * 128;
            int k8rel = c >> 8, rem = c & 255;
            const float* gs = A + (((size_t)(t * 4 + k8rel) * NM16 + bm16) * 32 + rem) * 4;
            cp_async16(as + c * 4, gs);
        }
#pragma unroll
        for (int i = 0; i < 8; i++) {
            int c = tid + i * 128;
            int k16rel = c >> 9, rem = c & 511;
            const float* gs = B + (((size_t)(t * 2 + k16rel) * NN8 + bn8) * 32 + rem) * 4;
            cp_async16(bs + c * 4, gs);
        }
    };

    issue_tile(0); CP_COMMIT();
    issue_tile(1); CP_COMMIT();

    for (int t = 0; t < ntiles; t++) {
        CP_WAIT(1);
        __syncthreads();
        if (t + 2 < ntiles) issue_tile(t + 2);
        CP_COMMIT();

        const float* as = sA + (t % GSTG) * GSTAGE_F;
        const float* bs = sB + (t % GSTG) * GSTAGE_F;

#pragma unroll
        for (int k16 = 0; k16 < 2; k16++) {
            float4 bq[8];
#pragma unroll
            for (int j = 0; j < 8; j++)
                bq[j] = *(const float4*)&bs[(k16 * 16 + wn * 8 + j) * 128 + lane * 4];

#pragma unroll
            for (int odd = 0; odd < 2; odd++) {
                int kk8 = k16 * 2 + odd;
                float4 aq[4];
#pragma unroll
                for (int i = 0; i < 4; i++)
                    aq[i] = *(const float4*)&as[(kk8 * 8 + wm * 4 + i) * 128 + lane * 4];

#pragma unroll
                for (int i = 0; i < 4; i++) {
                    uint32_t af[4] = { f2u(aq[i].x), f2u(aq[i].y),
                                       f2u(aq[i].z), f2u(aq[i].w) };
#pragma unroll
                    for (int j = 0; j < 8; j++) {
                        uint32_t bf[2];
                        if (odd == 0) { bf[0] = f2u(bq[j].x); bf[1] = f2u(bq[j].y); }
                        else          { bf[0] = f2u(bq[j].z); bf[1] = f2u(bq[j].w); }
                        mma_tf32(acc[i][j], af, bf);
                    }
                }
            }
        }
    }

    if (PACK_V) {
#pragma unroll
        for (int i = 0; i < 4; i++) {
#pragma unroll
            for (int hh = 0; hh < 2; hh++) {
                int R = bm + wm * 64 + i * 16 + g + hh * 8;
                int b = R >> 11, s = R & 2047;
                size_t rowbase = ((size_t)(b * 16) * 128 + (s >> 4)) * 2048;
                int soff = (s & 3) * 4 + ((s >> 2) & 3);
#pragma unroll
                for (int j = 0; j < 8; j++) {
                    int c0 = bn + wn * 64 + j * 8 + tig * 2;
#pragma unroll
                    for (int e = 0; e < 2; e++) {
                        int C2 = c0 + e;
                        int h = C2 >> 7, nl = C2 & 127;
                        size_t idx = rowbase + (size_t)h * 128 * 2048
                                   + ((nl >> 3) * 128 + (nl & 7) * 16 + soff);
                        C[idx] = rtf32(acc[i][j][e + 2 * hh]);
                    }
                }
            }
        }
    } else {
#pragma unroll
        for (int i = 0; i < 4; i++) {
            size_t ra = (size_t)(bm + wm * 64 + i * 16 + g);
            size_t rb = ra + 8;
#pragma unroll
            for (int j = 0; j < 8; j++) {
                size_t c = (size_t)(bn + wn * 64 + j * 8 + tig * 2);
                float b0 = 0.f, b1 = 0.f;
                if (ADD_BIAS) { b0 = bias[c]; b1 = bias[c + 1]; }
                *(float2*)&C[ra * DIM + c] =
                    make_float2(acc[i][j][0] + b0, acc[i][j][1] + b1);
                *(float2*)&C[rb * DIM + c] =
                    make_float2(acc[i][j][2] + b0, acc[i][j][3] + b1);
            }
        }
    }
}

// ============================================================================
// Fused RMSNorm + RoPE; writes q in packed A-frag (g_qp), k in packed B-frag
// (g_xr), per (b, head). Values identical (rtf32-rounded).
// ============================================================================
__global__ __launch_bounds__(256) void rmsnorm_rope_kernel(
    const float* __restrict__ q, const float* __restrict__ k,
    float* __restrict__ qp, float* __restrict__ kp,
    const float* __restrict__ gq, const float* __restrict__ gk,
    const float* __restrict__ freqs)
{
    const int isq = (blockIdx.y == 0);
    const float* x = isq ? q : k;
    const float* g = isq ? gq : gk;
    const int row = blockIdx.x;
    const int b   = row >> 11;
    const int s   = row & (SEQ - 1);
    const float* xr = x + (size_t)row * DIM;
    const int tid = threadIdx.x;

    float4 a = ((const float4*)xr)[tid];
    float4 bb = ((const float4*)xr)[tid + 256];

    float ss = a.x*a.x + a.y*a.y + a.z*a.z + a.w*a.w
             + bb.x*bb.x + bb.y*bb.y + bb.z*bb.z + bb.w*bb.w;
#pragma unroll
    for (int o = 16; o > 0; o >>= 1)
        ss += __shfl_xor_sync(0xffffffffu, ss, o);

    __shared__ float red[8];
    if ((tid & 31) == 0) red[tid >> 5] = ss;
    __syncthreads();
    float tot = 0.f;
#pragma unroll
    for (int w = 0; w < 8; w++) tot += red[w];

    const float inv = rsqrtf(tot * (1.0f / (float)DIM) + 1e-6f);

    float4 ga = ((const float4*)g)[tid];
    float4 gb = ((const float4*)g)[tid + 256];
    const float* fr = freqs + (size_t)s * (HDIM / 2);

    auto store_packed = [&](int D, float val) {
        int h = D >> 7;
        if (isq) {
            int k8 = (D >> 3) & 15, d = D & 7;
            size_t idx = (((size_t)(b * 16 + h) * 16 + k8) * 128 + (s >> 4)) * 128
                       + ((s & 7) * 4 + (d & 3)) * 4 + ((s >> 3) & 1) + 2 * (d >> 2);
            qp[idx] = val;
        } else {
            int k16 = (D >> 4) & 7, e16 = D & 15;
            size_t idx = (((size_t)(b * 16 + h) * 8 + k16) * 256 + (s >> 3)) * 128
                       + ((s & 7) * 4 + (e16 & 3)) * 4 + (e16 >> 2);
            kp[idx] = val;
        }
    };

    {
        int p0 = 2 * tid, p1 = 2 * tid + 1;
        float s0, c0, s1, c1;
        sincosf(fr[p0 & 63], &s0, &c0);
        sincosf(fr[p1 & 63], &s1, &c1);
        float v0 = a.x * inv * ga.x, v1 = a.y * inv * ga.y;
        float v2 = a.z * inv * ga.z, v3 = a.w * inv * ga.w;
        int D = 4 * tid;
        store_packed(D + 0, rtf32(v0 * c0 - v1 * s0));
        store_packed(D + 1, rtf32(v0 * s0 + v1 * c0));
        store_packed(D + 2, rtf32(v2 * c1 - v3 * s1));
        store_packed(D + 3, rtf32(v2 * s1 + v3 * c1));
    }
    {
        int p0 = 512 + 2 * tid, p1 = 513 + 2 * tid;
        float s0, c0, s1, c1;
        sincosf(fr[p0 & 63], &s0, &c0);
        sincosf(fr[p1 & 63], &s1, &c1);
        float v0 = bb.x * inv * gb.x, v1 = bb.y * inv * gb.y;
        float v2 = bb.z * inv * gb.z, v3 = bb.w * inv * gb.w;
        int D = 1024 + 4 * tid;
        store_packed(D + 0, rtf32(v0 * c0 - v1 * s0));
        store_packed(D + 1, rtf32(v0 * s0 + v1 * c0));
        store_packed(D + 2, rtf32(v2 * c1 - v3 * s1));
        store_packed(D + 3, rtf32(v2 * s1 + v3 * c1));
    }
}

// ============================================================================
// Flash attention, fragment-packed, 512 threads (16 warps, 4x4 warp grid).
// QK warp tile 32x16, PV warp tile 32x32 — double the warps of round 15 to
// hide the softmax/barrier critical path. K double-buffered, V single.
// smem: Qs[16][8][128] | Ks 2x[8][8][128] | Vs[4][16][128] | Ss[8][8][128]
//       | m[128] l[128] rmax[128][4] rsum[128][4]
// ============================================================================
#define BLKQ    128
#define ATHR    512
#define SM_QS   0
#define SM_KS   16384
#define SM_VS   32768
#define SM_SS   40960
#define SM_M    49152
#define SM_L    49280
#define SM_RMAX 49408   /* [128][4] */
#define SM_RSUM 49920   /* [128][4] */
#define ATTN_SMEM_FLOATS 50432
#define ATTN_SMEM_BYTES  (ATTN_SMEM_FLOATS * 4)   /* 201728 */

__global__ __launch_bounds__(ATHR) void attn_kernel(
    const int* __restrict__ seq_lens,
    const float* __restrict__ qp, const float* __restrict__ kp,
    const float* __restrict__ vp)
{
    extern __shared__ float sm[];
    float* Qs   = sm + SM_QS;
    float* Ks   = sm + SM_KS;
    float* Vs   = sm + SM_VS;
    float* Ss   = sm + SM_SS;
    float* mrow = sm + SM_M;
    float* lrow = sm + SM_L;
    float* rmax = sm + SM_RMAX;
    float* rsum = sm + SM_RSUM;

    const int b  = blockIdx.z;
    const int h  = blockIdx.y;
    const int q0 = blockIdx.x * BLKQ;
    const int q016 = q0 >> 4;
    const int seqlen = seq_lens[b];
    const int tid  = threadIdx.x;
    const int warp = tid >> 5;
    const int lane = tid & 31;
    const int g    = lane >> 2;
    const int tig  = lane & 3;
    const int wm = warp >> 2;          // 0..3 (32-query rows)
    const int wn = warp & 3;           // 0..3
    const float scale = 0.08838834764831845f;

    const int bh = b * 16 + h;
    const int ntiles = (seqlen + 63) >> 6;

    auto issue_k = [&](int t) {
        float* ks = Ks + (t & 1) * 8192;
#pragma unroll
        for (int i = 0; i < 4; i++) {
            int c = tid + i * ATHR;                // 0..2047
            int k16 = c >> 8, n8rel = (c >> 5) & 7, w = c & 31;
            const float* gs = kp + ((((size_t)bh * 8 + k16) * 256 + t * 8 + n8rel) * 128 + w * 4);
            cp_async16(&ks[(k16 * 8 + n8rel) * 128 + w * 4], gs);
        }
    };
    auto issue_v = [&](int t) {
#pragma unroll
        for (int i = 0; i < 4; i++) {
            int c = tid + i * ATHR;                // 0..2047
            int k16rel = c >> 9, n8 = (c >> 5) & 15, w = c & 31;
            const float* gs = vp + ((((size_t)bh * 128 + t * 4 + k16rel) * 16 + n8) * 128 + w * 4);
            cp_async16(&Vs[(k16rel * 16 + n8) * 128 + w * 4], gs);
        }
    };

    issue_k(0); CP_COMMIT();

    // load packed Q (linear float4)
#pragma unroll
    for (int i = 0; i < 8; i++) {
        int idx = tid + i * ATHR;                  // 0..4095 float4 slots
        int k8 = idx >> 8, m16rel = (idx >> 5) & 7, w = idx & 31;
        const float4* src = (const float4*)(qp
            + ((((size_t)bh * 16 + k8) * 128 + q016 + m16rel) * 128 + w * 4));
        *(float4*)&Qs[(k8 * 8 + m16rel) * 128 + w * 4] = *src;
    }
    if (tid < BLKQ) { mrow[tid] = -1e30f; lrow[tid] = 0.f; }

    float oa[2][4][4];
#pragma unroll
    for (int i = 0; i < 2; i++)
#pragma unroll
        for (int j = 0; j < 4; j++)
#pragma unroll
            for (int u = 0; u < 4; u++) oa[i][j][u] = 0.f;

    for (int t = 0; t < ntiles; t++) {
        CP_WAIT(0);
        __syncthreads();                           // sync1: K(t) resident, V free
        issue_v(t); CP_COMMIT();                   // group: V(t)
        if (t + 1 < ntiles) issue_k(t + 1);
        CP_COMMIT();                               // group: K(t+1)

        const float* ks = Ks + (t & 1) * 8192;
        const int kv0 = t * 64;
        const int nvalid = seqlen - kv0;

        // ---- S = scale * Q @ K^T (128x64); warp tile 32x16 (2x2 tiles) ----
        float sa[2][2][4];
#pragma unroll
        for (int i = 0; i < 2; i++)
#pragma unroll
            for (int j = 0; j < 2; j++)
#pragma unroll
                for (int u = 0; u < 4; u++) sa[i][j][u] = 0.f;

#pragma unroll
        for (int k16 = 0; k16 < 8; k16++) {
            float4 bq[2];
#pragma unroll
            for (int j = 0; j < 2; j++)
                bq[j] = *(const float4*)&ks[(k16 * 8 + wn * 2 + j) * 128 + lane * 4];
#pragma unroll
            for (int odd = 0; odd < 2; odd++) {
                int kk8 = k16 * 2 + odd;
                float4 aq[2];
#pragma unroll
                for (int i = 0; i < 2; i++)
                    aq[i] = *(const float4*)&Qs[(kk8 * 8 + wm * 2 + i) * 128 + lane * 4];
#pragma unroll
                for (int i = 0; i < 2; i++) {
                    uint32_t af[4] = { f2u(aq[i].x), f2u(aq[i].y),
                                       f2u(aq[i].z), f2u(aq[i].w) };
#pragma unroll
                    for (int j = 0; j < 2; j++) {
                        uint32_t bf[2];
                        if (odd == 0) { bf[0] = f2u(bq[j].x); bf[1] = f2u(bq[j].y); }
                        else          { bf[0] = f2u(bq[j].z); bf[1] = f2u(bq[j].w); }
                        mma_tf32(sa[i][j], af, bf);
                    }
                }
            }
        }

        // ---- masked row maxes -> rmax[128][4] ----
        float pmax[2][2];
#pragma unroll
        for (int i = 0; i < 2; i++)
#pragma unroll
            for (int hh = 0; hh < 2; hh++) pmax[i][hh] = -1e30f;
#pragma unroll
        for (int i = 0; i < 2; i++)
#pragma unroll
            for (int j = 0; j < 2; j++) {
                int cl = wn * 16 + j * 8 + tig * 2;
                bool v0 = cl < nvalid, v1 = (cl + 1) < nvalid;
#pragma unroll
                for (int u = 0; u < 4; u++) sa[i][j][u] *= scale;
                if (v0) { pmax[i][0] = fmaxf(pmax[i][0], sa[i][j][0]);
                          pmax[i][1] = fmaxf(pmax[i][1], sa[i][j][2]); }
                if (v1) { pmax[i][0] = fmaxf(pmax[i][0], sa[i][j][1]);
                          pmax[i][1] = fmaxf(pmax[i][1], sa[i][j][3]); }
            }
#pragma unroll
        for (int i = 0; i < 2; i++)
#pragma unroll
            for (int hh = 0; hh < 2; hh++) {
                float v = pmax[i][hh];
                v = fmaxf(v, __shfl_xor_sync(0xffffffffu, v, 1));
                v = fmaxf(v, __shfl_xor_sync(0xffffffffu, v, 2));
                pmax[i][hh] = v;
            }
        if (tig == 0) {
#pragma unroll
            for (int i = 0; i < 2; i++)
#pragma unroll
                for (int hh = 0; hh < 2; hh++)
                    rmax[(wm * 32 + i * 16 + g + hh * 8) * 4 + wn] = pmax[i][hh];
        }
        __syncthreads();                           // sync2: rmax ready, Ks consumed

        // ---- exp + store P (packed A-frag) + partial sums ----
        float mnewr[2][2], rscr[2][2], psum[2][2];
#pragma unroll
        for (int i = 0; i < 2; i++)
#pragma unroll
            for (int hh = 0; hh < 2; hh++) {
                int r = wm * 32 + i * 16 + g + hh * 8;
                float vmax = fmaxf(fmaxf(rmax[r * 4 + 0], rmax[r * 4 + 1]),
                                   fmaxf(rmax[r * 4 + 2], rmax[r * 4 + 3]));
                float mold = mrow[r];
                float mnew = fmaxf(mold, vmax);
                mnewr[i][hh] = mnew;
                rscr[i][hh]  = __expf(mold - mnew);
                psum[i][hh]  = 0.f;
            }
        const int c3  = (tig * 2) & 3;             // 0 or 2
        const int cb2 = (tig >> 1) * 2;
#pragma unroll
        for (int i = 0; i < 2; i++) {
            int m16rel = wm * 2 + i;
#pragma unroll
            for (int j = 0; j < 2; j++) {
                int cl = wn * 16 + j * 8 + tig * 2;
                bool v0 = cl < nvalid, v1 = (cl + 1) < nvalid;
                float p00 = v0 ? __expf(sa[i][j][0] - mnewr[i][0]) : 0.f;
                float p01 = v1 ? __expf(sa[i][j][1] - mnewr[i][0]) : 0.f;
                float p10 = v0 ? __expf(sa[i][j][2] - mnewr[i][1]) : 0.f;
                float p11 = v1 ? __expf(sa[i][j][3] - mnewr[i][1]) : 0.f;
                psum[i][0] += p00 + p01;
                psum[i][1] += p10 + p11;
                int base = ((wn * 2 + j) * 8 + m16rel) * 128 + g * 16;
                Ss[base + c3 * 4 + cb2 + 0]       = rtf32(p00);
                Ss[base + (c3 + 1) * 4 + cb2 + 0] = rtf32(p01);
                Ss[base + c3 * 4 + cb2 + 1]       = rtf32(p10);
                Ss[base + (c3 + 1) * 4 + cb2 + 1] = rtf32(p11);
            }
        }
#pragma unroll
        for (int i = 0; i < 2; i++)
#pragma unroll
            for (int hh = 0; hh < 2; hh++) {
                float v = psum[i][hh];
                v += __shfl_xor_sync(0xffffffffu, v, 1);
                v += __shfl_xor_sync(0xffffffffu, v, 2);
                psum[i][hh] = v;
            }
        if (tig == 0) {
#pragma unroll
            for (int i = 0; i < 2; i++)
#pragma unroll
                for (int hh = 0; hh < 2; hh++)
                    rsum[(wm * 32 + i * 16 + g + hh * 8) * 4 + wn] = psum[i][hh];
        }
#pragma unroll
        for (int i = 0; i < 2; i++)
#pragma unroll
            for (int j = 0; j < 4; j++) {
                oa[i][j][0] *= rscr[i][0]; oa[i][j][1] *= rscr[i][0];
                oa[i][j][2] *= rscr[i][1]; oa[i][j][3] *= rscr[i][1];
            }
        CP_WAIT(1);                                // V(t) resident (K(t+1) in flight)
        __syncthreads();                           // sync3: Ss + rsum + Vs visible

        if (wn == 0 && tig == 0) {
#pragma unroll
            for (int i = 0; i < 2; i++)
#pragma unroll
                for (int hh = 0; hh < 2; hh++) {
                    int r = wm * 32 + i * 16 + g + hh * 8;
                    float tot = (rsum[r * 4 + 0] + rsum[r * 4 + 1])
                              + (rsum[r * 4 + 2] + rsum[r * 4 + 3]);
                    lrow[r] = lrow[r] * rscr[i][hh] + tot;
                    mrow[r] = mnewr[i][hh];
                }
        }

        // ---- O += P @ V (128x128); warp tile 32x32 (2x4 tiles) ----
#pragma unroll
        for (int k16r = 0; k16r < 4; k16r++) {
            float4 bq[4];
#pragma unroll
            for (int j = 0; j < 4; j++)
                bq[j] = *(const float4*)&Vs[(k16r * 16 + wn * 4 + j) * 128 + lane * 4];
#pragma unroll
            for (int odd = 0; odd < 2; odd++) {
                int kk8 = k16r * 2 + odd;
                float4 aq[2];
#pragma unroll
                for (int i = 0; i < 2; i++)
                    aq[i] = *(const float4*)&Ss[(kk8 * 8 + wm * 2 + i) * 128 + lane * 4];
#pragma unroll
                for (int i = 0; i < 2; i++) {
                    uint32_t af[4] = { f2u(aq[i].x), f2u(aq[i].y),
                                       f2u(aq[i].z), f2u(aq[i].w) };
#pragma unroll
                    for (int j = 0; j < 4; j++) {
                        uint32_t bf[2];
                        if (odd == 0) { bf[0] = f2u(bq[j].x); bf[1] = f2u(bq[j].y); }
                        else          { bf[0] = f2u(bq[j].z); bf[1] = f2u(bq[j].w); }
                        mma_tf32(oa[i][j], af, bf);
                    }
                }
            }
        }
    }

    __syncthreads();

    // ---- write attn = O / l, rounded (row-major; repacked for O-proj) ----
#pragma unroll
    for (int i = 0; i < 2; i++) {
        int r0 = wm * 32 + i * 16 + g;
        float invl0 = 1.0f / lrow[r0];
        float invl1 = 1.0f / lrow[r0 + 8];
        size_t row0 = (size_t)(b * SEQ + q0 + r0) * DIM + h * HDIM;
        size_t row1 = row0 + (size_t)8 * DIM;
#pragma unroll
        for (int j = 0; j < 4; j++) {
            int c = wn * 32 + j * 8 + tig * 2;
            *(float2*)&g_attn[row0 + c] =
                make_float2(rtf32(oa[i][j][0] * invl0), rtf32(oa[i][j][1] * invl0));
            *(float2*)&g_attn[row1 + c] =
                make_float2(rtf32(oa[i][j][2] * invl1), rtf32(oa[i][j][3] * invl1));
        }
    }
}

// ============================================================================
extern "C" void kernel_launch(void* const* d_in, const int* in_sizes, int n_in,
                              void* d_out, int out_size)
{
    const float* x        = (const float*)d_in[0];
    const int*   seq_lens = (const int*)d_in[1];
    /* d_in[2] grid_sizes (int64) — unused by reference */
    const float* freqs    = (const float*)d_in[3];
    const float* Wq       = (const float*)d_in[4];
    const float* Wk       = (const float*)d_in[5];
    const float* Wv       = (const float*)d_in[6];
    const float* Wo       = (const float*)d_in[7];
    const float* bo       = (const float*)d_in[8];
    const float* gq       = (const float*)d_in[9];
    const float* gk       = (const float*)d_in[10];
    float* out = (float*)d_out;

    cudaFuncSetAttribute((const void*)gemm_mma_tf32<false, false>,
                         cudaFuncAttributeMaxDynamicSharedMemorySize, GEMM_SMEM_BYTES);
    cudaFuncSetAttribute((const void*)gemm_mma_tf32<false, true>,
                         cudaFuncAttributeMaxDynamicSharedMemorySize, GEMM_SMEM_BYTES);
    cudaFuncSetAttribute((const void*)gemm_mma_tf32<true, false>,
                         cudaFuncAttributeMaxDynamicSharedMemorySize, GEMM_SMEM_BYTES);
    cudaFuncSetAttribute((const void*)attn_kernel,
                         cudaFuncAttributeMaxDynamicSharedMemorySize, ATTN_SMEM_BYTES);

    float *pq, *pk, *pv, *pa, *pxr, *pqp, *pwr;
    cudaGetSymbolAddress((void**)&pq,  g_q);
    cudaGetSymbolAddress((void**)&pk,  g_k);
    cudaGetSymbolAddress((void**)&pv,  g_v);
    cudaGetSymbolAddress((void**)&pa,  g_attn);
    cudaGetSymbolAddress((void**)&pxr, g_xr);
    cudaGetSymbolAddress((void**)&pqp, g_qp);
    cudaGetSymbolAddress((void**)&pwr, g_wr4);

    const dim3 ggrid(DIM / 128, MROWS / 128);     // (16, 32)
    const size_t WSZ = (size_t)DIM * DIM;

    // fragment-pack (+ tf32-round) x and weights
    repack_a_kernel<<<dim3(DIM / 32, MROWS / 64), 256>>>(x, pxr);
    repack_b4_kernel<<<dim3(DIM / 32, DIM / 64, 4), 256>>>(Wq, Wk, Wv, Wo, pwr);

    gemm_mma_tf32<false, false><<<ggrid, 128, GEMM_SMEM_BYTES>>>(pxr, pwr,           pq, nullptr);
    gemm_mma_tf32<false, false><<<ggrid, 128, GEMM_SMEM_BYTES>>>(pxr, pwr + WSZ,     pk, nullptr);
    gemm_mma_tf32<false, true ><<<ggrid, 128, GEMM_SMEM_BYTES>>>(pxr, pwr + 2 * WSZ, pv, nullptr); // V packed

    // rmsnorm+rope: q -> packed A-frag (g_qp), k -> packed B-frag (g_xr)
    rmsnorm_rope_kernel<<<dim3(MROWS, 2), 256>>>(pq, pk, pqp, pxr, gq, gk, freqs);

    attn_kernel<<<dim3(SEQ / BLKQ, HEADS, BATCH), ATHR, ATTN_SMEM_BYTES>>>(
        seq_lens, pqp, pxr, pv);

    // repack attention output for the O-projection (g_xr free after attention)
    repack_a_kernel<<<dim3(DIM / 32, MROWS / 64), 256>>>(pa, pxr);

    gemm_mma_tf32<true, false><<<ggrid, 128, GEMM_SMEM_BYTES>>>(pxr, pwr + 3 * WSZ, out, bo);
}